// round 10
// baseline (speedup 1.0000x reference)
#include <cuda_runtime.h>
#include <cuda_fp16.h>

// (B,C,D,H,W) = (4,8,16,256,256), k=3, stride=1, pad=1
#define BC    32
#define DD    16
#define HH    256
#define WW    256
#define HW    (HH*WW)
#define CHV   (DD*HW)

#define TH    16              // tile height (= #warps)
#define TWPIX 128             // tile width in pixels (4 px / lane)
#define ROWS  (TH+2)          // 18
#define COLS  136             // col3 = w0-1 halo, cols4..131 data, col132 = w0+128 halo
#define TS    (ROWS*COLS)     // 2448 half2 cells
#define NPAIR (TS/2)          // 1224
#define NT    512
#define ZS    8               // z-slices per CTA

__device__ __forceinline__ __half2 u2h(unsigned int u) {
    return *reinterpret_cast<__half2*>(&u);
}
__device__ __forceinline__ unsigned int h2u(__half2 h) {
    return *reinterpret_cast<unsigned int*>(&h);
}

__global__ void __launch_bounds__(NT, 2)
softargmax_kernel(const float* __restrict__ x, float* __restrict__ out)
{
    const int bc = blockIdx.z & 31;
    const int d0 = (blockIdx.z >> 5) * ZS;
    const int h0 = blockIdx.y * TH;
    const int w0 = blockIdx.x * TWPIX;
    const int tid = threadIdx.x;
    const int tx = tid & 31;
    const int ty = tid >> 5;

    __shared__ __align__(16) __half2 tile[2][TS];

    const float* __restrict__ xc = x + (size_t)bc * CHV;

    // 3 pair-fill slots cover NPAIR=1224 (slot2: tid<200). One pair = 2 cells.
    int  offA[3], offB[3];
    bool prA[3], prB[3], inr[3];
    #pragma unroll
    for (int j = 0; j < 3; j++) {
        int pidx = tid + j * NT;
        inr[j] = (pidx < NPAIR);
        int r  = pidx / (COLS / 2);          // 68 pairs per row
        int c0 = 2 * (pidx % (COLS / 2));
        int hh = h0 + r - 1;
        int wwA = w0 + c0 - 4, wwB = wwA + 1;
        bool hok = inr[j] && (hh >= 0) && (hh < HH);
        prA[j] = hok && (c0 >= 4) && (c0 <= 132) && (wwA >= 0) && (wwA < WW);
        prB[j] = hok && (c0 + 1 >= 3) && (c0 + 1 <= 132) && (wwB >= 0) && (wwB < WW);
        offA[j] = prA[j] ? hh * WW + wwA : 0;
        offB[j] = prB[j] ? hh * WW + wwB : 0;
    }

    float rvA[3], rvB[3];

    #define LOADSLICE(ptr)                                                    \
        _Pragma("unroll")                                                     \
        for (int j = 0; j < 3; j++) {                                         \
            rvA[j] = prA[j] ? __ldg((ptr) + offA[j]) : 0.f;                   \
            rvB[j] = prB[j] ? __ldg((ptr) + offB[j]) : 0.f;                   \
        }

    #define PUBLISH(BUF)                                                      \
        _Pragma("unroll")                                                     \
        for (int j = 0; j < 3; j++) {                                         \
            if (inr[j]) {                                                     \
                float eA = prA[j] ? __expf(rvA[j]) : 0.f;                     \
                float eB = prB[j] ? __expf(rvB[j]) : 0.f;                     \
                uint2 val = make_uint2(                                       \
                    h2u(__floats2half2_rn(eA, eA * rvA[j])),                  \
                    h2u(__floats2half2_rn(eB, eB * rvB[j])));                 \
                *reinterpret_cast<uint2*>(&tile[BUF][2 * (tid + j * NT)]) = val; \
            }                                                                 \
        }

    // s[0..3]=(Σe,Σv) px0..3 ; s[4..7]=xnum ; s[8..11]=ynum
    #define ACCUM(s, BUF)                                                     \
        _Pragma("unroll")                                                     \
        for (int r = 0; r < 3; r++) {                                         \
            const uint4 u = *reinterpret_cast<const uint4*>(                  \
                &tile[BUF][(ty + r) * COLS + 4 + 4 * tx]);                    \
            unsigned int uL = __shfl_up_sync(0xFFFFFFFFu, u.w, 1);            \
            unsigned int uR = __shfl_down_sync(0xFFFFFFFFu, u.x, 1);          \
            if (tx == 0)                                                      \
                uL = *reinterpret_cast<const unsigned int*>(                  \
                    &tile[BUF][(ty + r) * COLS + 3]);                         \
            if (tx == 31)                                                     \
                uR = *reinterpret_cast<const unsigned int*>(                  \
                    &tile[BUF][(ty + r) * COLS + 132]);                       \
            const __half2 q0 = u2h(u.x), q1 = u2h(u.y);                       \
            const __half2 q2 = u2h(u.z), q3 = u2h(u.w);                       \
            const __half2 L = u2h(uL), R = u2h(uR);                           \
            const __half2 t01 = __hadd2(q0, q1);                              \
            const __half2 t12 = __hadd2(q1, q2);                              \
            const __half2 t23 = __hadd2(q2, q3);                              \
            const __half2 rs0 = __hadd2(L, t01);                              \
            const __half2 rs1 = __hadd2(t01, q2);                             \
            const __half2 rs2 = __hadd2(t12, q3);                             \
            const __half2 rs3 = __hadd2(t23, R);                              \
            (s)[0] = __hadd2((s)[0], rs0);  (s)[1] = __hadd2((s)[1], rs1);    \
            (s)[2] = __hadd2((s)[2], rs2);  (s)[3] = __hadd2((s)[3], rs3);    \
            (s)[4] = __hadd2((s)[4], __hsub2(q1, L));                         \
            (s)[5] = __hadd2((s)[5], __hsub2(q2, q0));                        \
            (s)[6] = __hadd2((s)[6], __hsub2(q3, q1));                        \
            (s)[7] = __hadd2((s)[7], __hsub2(R, q2));                         \
            if (r == 0) {                                                     \
                (s)[8]  = __hsub2((s)[8],  rs0); (s)[9]  = __hsub2((s)[9],  rs1); \
                (s)[10] = __hsub2((s)[10], rs2); (s)[11] = __hsub2((s)[11], rs3); \
            }                                                                 \
            if (r == 2) {                                                     \
                (s)[8]  = __hadd2((s)[8],  rs0); (s)[9]  = __hadd2((s)[9],  rs1); \
                (s)[10] = __hadd2((s)[10], rs2); (s)[11] = __hadd2((s)[11], rs3); \
            }                                                                 \
        }

    const __half2 zero = __floats2half2_rn(0.f, 0.f);
    __half2 p[12], c[12], n[12];
    #pragma unroll
    for (int k = 0; k < 12; k++) { p[k] = zero; c[k] = zero; }

    // ---- prologue: slice d0-1 (if any) -> buf0, slice d0 -> buf1 ----
    if (d0 > 0) {
        LOADSLICE(xc + (size_t)(d0 - 1) * HW);
        PUBLISH(0);
    }
    LOADSLICE(xc + (size_t)d0 * HW);
    PUBLISH(1);
    LOADSLICE(xc + (size_t)(d0 + 1) * HW);   // prefetch slice d0+1 (d0+1 <= 9 < DD)
    __syncthreads();
    if (d0 > 0) ACCUM(p, 0);
    ACCUM(c, 1);
    __syncthreads();   // protect buf0/buf1 reads above from dd=0/1 publishes

    const float hf = (float)(h0 + ty);
    const float wf = (float)(w0 + 4 * tx);
    const size_t pixbase = (size_t)(h0 + ty) * WW + (w0 + 4 * tx);
    float* pcoord = out + (size_t)bc * 3 * CHV + (size_t)d0 * HW + pixbase;
    float* pval   = out + (size_t)BC * 3 * CHV + (size_t)bc * CHV
                        + (size_t)d0 * HW + pixbase;

    #pragma unroll 4
    for (int dd = 0; dd < ZS; dd++) {
        const int d = d0 + dd;
        #pragma unroll
        for (int k = 0; k < 12; k++) n[k] = zero;

        if (d + 1 < DD) {
            const int buf = dd & 1;
            PUBLISH(buf);                        // slice d+1 (from rv)
            if (dd < ZS - 1 && d + 2 < DD) {     // prefetch slice d+2 (bounded!)
                LOADSLICE(xc + (size_t)(d + 2) * HW);
            }
            __syncthreads();                     // one barrier per slice
            ACCUM(n, buf);
        }

        float4 z4, x4, y4, v4;
        #pragma unroll
        for (int i = 0; i < 4; i++) {
            const __half2 T = __hadd2(__hadd2(p[i], c[i]), n[i]);
            const float den = __low2float(T) + 1e-8f;
            const float inv = __fdividef(1.0f, den);
            const float zn  = __low2float(__hsub2(n[i], p[i]));
            const float xnf = __low2float(__hadd2(__hadd2(p[4 + i], c[4 + i]), n[4 + i]));
            const float ynf = __low2float(__hadd2(__hadd2(p[8 + i], c[8 + i]), n[8 + i]));
            (&z4.x)[i] = (float)d + zn * inv;
            (&x4.x)[i] = wf + (float)i + xnf * inv;
            (&y4.x)[i] = hf + ynf * inv;
            (&v4.x)[i] = __high2float(T) * inv;
        }

        __stcs(reinterpret_cast<float4*>(pcoord),           z4);
        __stcs(reinterpret_cast<float4*>(pcoord + CHV),     x4);
        __stcs(reinterpret_cast<float4*>(pcoord + 2 * CHV), y4);
        __stcs(reinterpret_cast<float4*>(pval),             v4);

        pcoord += HW;
        pval   += HW;

        #pragma unroll
        for (int k = 0; k < 12; k++) { p[k] = c[k]; c[k] = n[k]; }
    }
}

extern "C" void kernel_launch(void* const* d_in, const int* in_sizes, int n_in,
                              void* d_out, int out_size) {
    const float* x = (const float*)d_in[0];
    float* out = (float*)d_out;
    // grid: 2 W-tiles x 16 H-tiles x (32 bc * 2 z-halves) = 2048 CTAs
    softargmax_kernel<<<dim3(WW / TWPIX, HH / TH, BC * (DD / ZS)), NT>>>(x, out);
}

// round 11
// speedup vs baseline: 1.0337x; 1.0337x over previous
#include <cuda_runtime.h>
#include <cuda_fp16.h>

// (B,C,D,H,W) = (4,8,16,256,256), k=3, stride=1, pad=1
#define BC    32
#define DD    16
#define HH    256
#define WW    256
#define HW    (HH*WW)
#define CHV   (DD*HW)

#define TH     16             // tile height (= #warps)
#define TWPIX  64             // tile width in pixels (2 px / lane)
#define ROWS   (TH+2)         // 18
#define COLS   68             // col1 = w0-1 halo, cols2..65 data, col66 = w0+64 halo
#define TS     (ROWS*COLS)    // 1224 half2 cells
#define NPAIRS (TS/2)         // 612
#define PPR    (COLS/2)       // 34 pairs per row
#define NT     (TH*32)        // 512

__device__ __forceinline__ __half2 u2h(unsigned int u) {
    return *reinterpret_cast<__half2*>(&u);
}
__device__ __forceinline__ unsigned int h2u(__half2 h) {
    return *reinterpret_cast<unsigned int*>(&h);
}

__global__ void __launch_bounds__(NT, 2)
softargmax_kernel(const float* __restrict__ x, float* __restrict__ out)
{
    const int bc = blockIdx.z;
    const int h0 = blockIdx.y * TH;
    const int w0 = blockIdx.x * TWPIX;
    const int tid = threadIdx.x;
    const int tx = tid & 31;
    const int ty = tid >> 5;

    // 4-deep rotation of half2(e, e*x) slice tiles
    __shared__ __align__(16) __half2 tile[4][TS];

    const float* __restrict__ xc = x + (size_t)bc * CHV;

    // ---- per-slot (pair) fill state: 2 slots cover 612 pairs ----
    int  base[2], offB[2];
    bool vA[2], vB[2], v2[2], inp[2];
    #pragma unroll
    for (int j = 0; j < 2; j++) {
        int P = tid + j * NT;
        inp[j] = (P < NPAIRS);
        int r  = P / PPR;
        int c0 = 2 * (P % PPR);
        int hh = h0 + r - 1;
        bool hok = inp[j] && (hh >= 0) && (hh < HH);
        int wwA = w0 + c0 - 2;
        int wwB = wwA + 1;
        vA[j] = hok && (c0 >= 2) && (c0 <= 66) && (wwA >= 0) && (wwA < WW);
        vB[j] = hok && (c0 + 1 <= 66) && (wwB >= 0) && (wwB < WW);
        v2[j] = vA[j] && vB[j];
        base[j] = vA[j] ? hh * WW + wwA : 0;
        offB[j] = vB[j] ? hh * WW + wwB : 0;
    }

    float ra[2], rb[2], ra2[2], rb2[2];   // raw values for 2 in-flight slices

    #define LOADSLICE(ptr, RA, RB)                                            \
        _Pragma("unroll")                                                     \
        for (int j = 0; j < 2; j++) {                                         \
            RA[j] = 0.f; RB[j] = 0.f;                                         \
            if (v2[j]) {                                                      \
                float2 t = __ldg(reinterpret_cast<const float2*>((ptr) + base[j])); \
                RA[j] = t.x; RB[j] = t.y;                                     \
            } else {                                                          \
                if (vA[j]) RA[j] = __ldg((ptr) + base[j]);                    \
                if (vB[j]) RB[j] = __ldg((ptr) + offB[j]);                    \
            }                                                                 \
        }

    #define PUBLISH(BUF, RA, RB)                                              \
        _Pragma("unroll")                                                     \
        for (int j = 0; j < 2; j++) {                                         \
            if (inp[j]) {                                                     \
                float eA = vA[j] ? __expf(RA[j]) : 0.f;                       \
                float eB = vB[j] ? __expf(RB[j]) : 0.f;                       \
                uint2 val = make_uint2(                                       \
                    h2u(__floats2half2_rn(eA, eA * RA[j])),                   \
                    h2u(__floats2half2_rn(eB, eB * RB[j])));                  \
                *reinterpret_cast<uint2*>(&tile[BUF][2 * (tid + j * NT)]) = val; \
            }                                                                 \
        }

    // s[0]=(Σe,Σv) px0  s[1]=xnum px0  s[2]=ynum px0 ; s[3..5] px1
    #define ACCUM(s, BUF)                                                     \
        _Pragma("unroll")                                                     \
        for (int r = 0; r < 3; r++) {                                         \
            const uint2 u = *reinterpret_cast<const uint2*>(                  \
                &tile[BUF][(ty + r) * COLS + 2 + 2 * tx]);                    \
            unsigned int uL = __shfl_up_sync(0xFFFFFFFFu, u.y, 1);            \
            unsigned int uR = __shfl_down_sync(0xFFFFFFFFu, u.x, 1);          \
            if (tx == 0)                                                      \
                uL = *reinterpret_cast<const unsigned int*>(                  \
                    &tile[BUF][(ty + r) * COLS + 1]);                         \
            if (tx == 31)                                                     \
                uR = *reinterpret_cast<const unsigned int*>(                  \
                    &tile[BUF][(ty + r) * COLS + 66]);                        \
            const __half2 hc0 = u2h(u.x), hc1 = u2h(u.y);                     \
            const __half2 hL = u2h(uL), hR = u2h(uR);                         \
            const __half2 t = __hadd2(hc0, hc1);                              \
            const __half2 rs0 = __hadd2(hL, t);                               \
            const __half2 rs1 = __hadd2(t, hR);                               \
            (s)[0] = __hadd2((s)[0], rs0);                                    \
            (s)[3] = __hadd2((s)[3], rs1);                                    \
            (s)[1] = __hadd2((s)[1], __hsub2(hc1, hL));                       \
            (s)[4] = __hadd2((s)[4], __hsub2(hR, hc0));                       \
            if (r == 0) { (s)[2] = __hsub2((s)[2], rs0);                      \
                          (s)[5] = __hsub2((s)[5], rs1); }                    \
            if (r == 2) { (s)[2] = __hadd2((s)[2], rs0);                      \
                          (s)[5] = __hadd2((s)[5], rs1); }                    \
        }

    // emit one z-slice's 2 pixels from window sums (P,C,N)
    #define EPILOGUE(DV, P, C, N)                                             \
        do {                                                                  \
            const __half2 T0 = __hadd2(__hadd2((P)[0], (C)[0]), (N)[0]);      \
            const __half2 T1 = __hadd2(__hadd2((P)[3], (C)[3]), (N)[3]);      \
            const float inv0 = __fdividef(1.0f, __low2float(T0) + 1e-8f);     \
            const float inv1 = __fdividef(1.0f, __low2float(T1) + 1e-8f);     \
            const float df = (float)(DV);                                     \
            float2 z2 = make_float2(                                          \
                df + __low2float(__hsub2((N)[0], (P)[0])) * inv0,             \
                df + __low2float(__hsub2((N)[3], (P)[3])) * inv1);            \
            float2 x2 = make_float2(                                          \
                wf + __low2float(__hadd2(__hadd2((P)[1], (C)[1]), (N)[1])) * inv0, \
                wf + 1.f + __low2float(__hadd2(__hadd2((P)[4], (C)[4]), (N)[4])) * inv1); \
            float2 y2 = make_float2(                                          \
                hf + __low2float(__hadd2(__hadd2((P)[2], (C)[2]), (N)[2])) * inv0, \
                hf + __low2float(__hadd2(__hadd2((P)[5], (C)[5]), (N)[5])) * inv1); \
            float2 v2o = make_float2(__high2float(T0) * inv0,                 \
                                     __high2float(T1) * inv1);                \
            __stcs(reinterpret_cast<float2*>(pcoord),           z2);          \
            __stcs(reinterpret_cast<float2*>(pcoord + CHV),     x2);          \
            __stcs(reinterpret_cast<float2*>(pcoord + 2 * CHV), y2);          \
            __stcs(reinterpret_cast<float2*>(pval),             v2o);         \
            pcoord += HW;                                                     \
            pval   += HW;                                                     \
        } while (0)

    const __half2 zero = __floats2half2_rn(0.f, 0.f);
    __half2 p[6], c[6], n[6], m[6];
    #pragma unroll
    for (int k = 0; k < 6; k++) { p[k] = zero; c[k] = zero; }

    // ---- prologue: slice 0 -> buf0, prefetch slices 1, 2 ----
    LOADSLICE(xc, ra, rb);
    PUBLISH(0, ra, rb);
    LOADSLICE(xc + HW, ra, rb);
    LOADSLICE(xc + 2 * (size_t)HW, ra2, rb2);
    __syncthreads();
    ACCUM(c, 0);

    const float hf = (float)(h0 + ty);
    const float wf = (float)(w0 + 2 * tx);
    const size_t pixbase = (size_t)(h0 + ty) * WW + (w0 + 2 * tx);
    float* pcoord = out + (size_t)bc * 3 * CHV + pixbase;
    float* pval   = out + (size_t)BC * 3 * CHV + (size_t)bc * CHV + pixbase;

    #pragma unroll
    for (int d = 0; d < DD; d += 2) {
        #pragma unroll
        for (int k = 0; k < 6; k++) { n[k] = zero; m[k] = zero; }

        // publish slices d+1 (always < DD) and d+2 (if valid)
        PUBLISH((d + 1) & 3, ra, rb);
        if (d + 2 < DD) PUBLISH((d + 2) & 3, ra2, rb2);
        // prefetch slices d+3, d+4
        if (d + 3 < DD) LOADSLICE(xc + (size_t)(d + 3) * HW, ra, rb);
        if (d + 4 < DD) LOADSLICE(xc + (size_t)(d + 4) * HW, ra2, rb2);
        __syncthreads();                         // ONE barrier per 2 slices
        ACCUM(n, (d + 1) & 3);
        if (d + 2 < DD) ACCUM(m, (d + 2) & 3);

        EPILOGUE(d,     p, c, n);                // output slice d
        EPILOGUE(d + 1, c, n, m);                // output slice d+1

        #pragma unroll
        for (int k = 0; k < 6; k++) { p[k] = n[k]; c[k] = m[k]; }
    }
}

extern "C" void kernel_launch(void* const* d_in, const int* in_sizes, int n_in,
                              void* d_out, int out_size) {
    const float* x = (const float*)d_in[0];
    float* out = (float*)d_out;
    softargmax_kernel<<<dim3(WW / TWPIX, HH / TH, BC), NT>>>(x, out);
}

// round 12
// speedup vs baseline: 1.1418x; 1.1045x over previous
#include <cuda_runtime.h>
#include <cuda_fp16.h>

// (B,C,D,H,W) = (4,8,16,256,256), k=3, stride=1, pad=1
#define BC   32
#define DD   16
#define HH   256
#define WW   256
#define HW   (HH*WW)
#define CHV  (DD*HW)

#define TH    16              // tile height (= #warps)
#define TWPIX 64              // tile width in pixels (2 px / lane)
#define ROWS  (TH+2)          // 18
#define COLS  68              // col1 = w0-1 halo, cols2..65 data, col66 = w0+64 halo
#define TS    (ROWS*COLS)     // 1224
#define NT    (TH*32)         // 512

__device__ __forceinline__ __half2 u2h(unsigned int u) {
    return *reinterpret_cast<__half2*>(&u);
}

__global__ void __launch_bounds__(NT, 2)
softargmax_kernel(const float* __restrict__ x, float* __restrict__ out)
{
    const int bc = blockIdx.z;
    const int h0 = blockIdx.y * TH;
    const int w0 = blockIdx.x * TWPIX;
    const int tid = threadIdx.x;
    const int tx = tid & 31;
    const int ty = tid >> 5;

    // double-buffered half2(e, e*x) slice tiles
    __shared__ __align__(16) __half2 tile[2][TS];

    const float* __restrict__ xc = x + (size_t)bc * CHV;

    // 3 fill slots cover TS=1224 (slot2 partial)
    int  off[3];
    bool inr[3], pred[3];
    #pragma unroll
    for (int j = 0; j < 3; j++) {
        int i = tid + j * NT;
        int r = i / COLS, c = i % COLS;
        int hh = h0 + r - 1;
        int ww = w0 + c - 2;
        inr[j]  = (i < TS);
        pred[j] = inr[j] && (c >= 1) && (c <= 66) &&
                  (hh >= 0) && (hh < HH) && (ww >= 0) && (ww < WW);
        off[j]  = pred[j] ? hh * WW + ww : 0;
    }

    float rv[3];
    #pragma unroll
    for (int j = 0; j < 3; j++) rv[j] = pred[j] ? __ldg(xc + off[j]) : 0.f;

    #define PUBLISH(BUF)                                                      \
        _Pragma("unroll")                                                     \
        for (int j = 0; j < 3; j++) {                                         \
            if (inr[j]) {                                                     \
                float e = pred[j] ? __expf(rv[j]) : 0.f;                      \
                tile[BUF][tid + j * NT] = __floats2half2_rn(e, e * rv[j]);    \
            }                                                                 \
        }

    // Separable 3x3: vertical reduce (colsum, ydiff) then horizontal stencil.
    // s[0]=(Σe,Σv) px0  s[1]=xnum px0  s[2]=ynum px0 ; s[3..5] px1
    #define ACCUM(s, BUF)                                                     \
        do {                                                                  \
            const int rb = (ty) * COLS + 2 + 2 * tx;                          \
            const uint2 u0 = *reinterpret_cast<const uint2*>(&tile[BUF][rb]); \
            const uint2 u1 = *reinterpret_cast<const uint2*>(                 \
                &tile[BUF][rb + COLS]);                                       \
            const uint2 u2 = *reinterpret_cast<const uint2*>(                 \
                &tile[BUF][rb + 2 * COLS]);                                   \
            const __half2 a0 = u2h(u0.x), a1 = u2h(u1.x), a2 = u2h(u2.x);     \
            const __half2 b0 = u2h(u0.y), b1 = u2h(u1.y), b2 = u2h(u2.y);     \
            __half2 cs0 = __hadd2(__hadd2(a0, a1), a2);                       \
            __half2 cs1 = __hadd2(__hadd2(b0, b1), b2);                       \
            __half2 yd0 = __hsub2(a2, a0);                                    \
            __half2 yd1 = __hsub2(b2, b0);                                    \
            __half2 csL, csR, ydL, ydR;                                       \
            {                                                                 \
                unsigned int t1, t2, t3, t4;                                  \
                t1 = __shfl_up_sync(0xFFFFFFFFu,                              \
                        *reinterpret_cast<unsigned int*>(&cs1), 1);           \
                t2 = __shfl_down_sync(0xFFFFFFFFu,                            \
                        *reinterpret_cast<unsigned int*>(&cs0), 1);           \
                t3 = __shfl_up_sync(0xFFFFFFFFu,                              \
                        *reinterpret_cast<unsigned int*>(&yd1), 1);           \
                t4 = __shfl_down_sync(0xFFFFFFFFu,                            \
                        *reinterpret_cast<unsigned int*>(&yd0), 1);           \
                csL = u2h(t1); csR = u2h(t2); ydL = u2h(t3); ydR = u2h(t4);   \
            }                                                                 \
            if (tx == 0) {                                                    \
                const int hb = (ty) * COLS + 1;                               \
                const __half2 g0 = tile[BUF][hb];                             \
                const __half2 g1 = tile[BUF][hb + COLS];                      \
                const __half2 g2 = tile[BUF][hb + 2 * COLS];                  \
                csL = __hadd2(__hadd2(g0, g1), g2);                           \
                ydL = __hsub2(g2, g0);                                        \
            }                                                                 \
            if (tx == 31) {                                                   \
                const int hb = (ty) * COLS + 66;                              \
                const __half2 g0 = tile[BUF][hb];                             \
                const __half2 g1 = tile[BUF][hb + COLS];                      \
                const __half2 g2 = tile[BUF][hb + 2 * COLS];                  \
                csR = __hadd2(__hadd2(g0, g1), g2);                           \
                ydR = __hsub2(g2, g0);                                        \
            }                                                                 \
            const __half2 t = __hadd2(cs0, cs1);                              \
            (s)[0] = __hadd2(csL, t);                                         \
            (s)[3] = __hadd2(t, csR);                                         \
            (s)[1] = __hsub2(cs1, csL);                                       \
            (s)[4] = __hsub2(csR, cs0);                                       \
            const __half2 ty2 = __hadd2(yd0, yd1);                            \
            (s)[2] = __hadd2(ydL, ty2);                                       \
            (s)[5] = __hadd2(ty2, ydR);                                       \
        } while (0)

    const __half2 zero = __floats2half2_rn(0.f, 0.f);
    __half2 p[6], c[6], n[6];
    #pragma unroll
    for (int k = 0; k < 6; k++) p[k] = zero;

    // prologue: slice 0 -> buf0
    PUBLISH(0);
    #pragma unroll
    for (int j = 0; j < 3; j++) rv[j] = pred[j] ? __ldg(xc + HW + off[j]) : 0.f;
    __syncthreads();
    ACCUM(c, 0);

    const float hf = (float)(h0 + ty);
    const float wf = (float)(w0 + 2 * tx);
    const size_t pixbase = (size_t)(h0 + ty) * WW + (w0 + 2 * tx);
    float* pcoord = out + (size_t)bc * 3 * CHV + pixbase;
    float* pval   = out + (size_t)BC * 3 * CHV + (size_t)bc * CHV + pixbase;

    #pragma unroll
    for (int d = 0; d < DD; d++) {
        if (d + 1 < DD) {
            const int buf = (d + 1) & 1;
            PUBLISH(buf);                       // slice d+1
            if (d + 2 < DD) {                   // prefetch slice d+2
                const float* xs2 = xc + (size_t)(d + 2) * HW;
                #pragma unroll
                for (int j = 0; j < 3; j++)
                    rv[j] = pred[j] ? __ldg(xs2 + off[j]) : 0.f;
            }
            __syncthreads();                    // one barrier per slice
            ACCUM(n, buf);
        } else {
            #pragma unroll
            for (int k = 0; k < 6; k++) n[k] = zero;
        }

        const __half2 tot0 = __hadd2(__hadd2(p[0], c[0]), n[0]);
        const __half2 tot1 = __hadd2(__hadd2(p[3], c[3]), n[3]);
        const float inv0 = __fdividef(1.0f, __low2float(tot0) + 1e-8f);
        const float inv1 = __fdividef(1.0f, __low2float(tot1) + 1e-8f);
        const float df = (float)d;

        float2 z2 = make_float2(
            df + __low2float(__hsub2(n[0], p[0])) * inv0,
            df + __low2float(__hsub2(n[3], p[3])) * inv1);
        float2 x2 = make_float2(
            wf       + __low2float(__hadd2(__hadd2(p[1], c[1]), n[1])) * inv0,
            wf + 1.f + __low2float(__hadd2(__hadd2(p[4], c[4]), n[4])) * inv1);
        float2 y2 = make_float2(
            hf + __low2float(__hadd2(__hadd2(p[2], c[2]), n[2])) * inv0,
            hf + __low2float(__hadd2(__hadd2(p[5], c[5]), n[5])) * inv1);
        float2 v2 = make_float2(__high2float(tot0) * inv0,
                                __high2float(tot1) * inv1);

        __stcs(reinterpret_cast<float2*>(pcoord),           z2);
        __stcs(reinterpret_cast<float2*>(pcoord + CHV),     x2);
        __stcs(reinterpret_cast<float2*>(pcoord + 2 * CHV), y2);
        __stcs(reinterpret_cast<float2*>(pval),             v2);

        pcoord += HW;
        pval   += HW;

        #pragma unroll
        for (int k = 0; k < 6; k++) { p[k] = c[k]; c[k] = n[k]; }
    }
}

extern "C" void kernel_launch(void* const* d_in, const int* in_sizes, int n_in,
                              void* d_out, int out_size) {
    const float* x = (const float*)d_in[0];
    float* out = (float*)d_out;
    softargmax_kernel<<<dim3(WW / TWPIX, HH / TH, BC), NT>>>(x, out);
}